// round 3
// baseline (speedup 1.0000x reference)
#include <cuda_runtime.h>

// Problem constants
#define B   128
#define S   37
#define T   2048
#define D   256
#define STC 8
#define C   2
#define MERGED 264     // D + STC
#define F2  74         // 2*S features
#define NT  256        // threads per block
#define NW  8          // warps per block
#define G   (T/4)      // 512 float4 groups along time

__device__ __forceinline__ float warp_sum(float v) {
#pragma unroll
    for (int o = 16; o; o >>= 1) v += __shfl_xor_sync(0xffffffffu, v, o);
    return v;
}

__global__ __launch_bounds__(NT, 1)
void enc_cls_fused_kernel(const float* __restrict__ x,
                          const float* __restrict__ static_in,
                          const float* __restrict__ time_in,
                          const int*   __restrict__ smask,
                          const float* __restrict__ W_sensor,  // [74,256]
                          const float* __restrict__ b_sensor,  // [256]
                          const float* __restrict__ W_time,    // [1,256]
                          const float* __restrict__ b_time,    // [256]
                          const float* __restrict__ W_static,  // [8,8]
                          const float* __restrict__ b_static,  // [8]
                          const float* __restrict__ W_merge,   // [264,264]
                          const float* __restrict__ b_merge,   // [264]
                          const float* __restrict__ W_cls,     // [264,2]
                          const float* __restrict__ b_cls,     // [2]
                          float* __restrict__ out)             // [B,2]
{
    __shared__ float red[NW][F2 + 2];   // per-warp partials: 74 feats + time + denom
    __shared__ float sfeat[F2];         // raw feature sums over valid timesteps
    __shared__ float ssum[2];           // raw (masked time sum, denom)
    __shared__ float s_inv, s_r, s_ts;
    __shared__ float scomb[MERGED];
    __shared__ float ored[NW][2];

    const int b    = blockIdx.x;
    const int tid  = threadIdx.x;
    const int lane = tid & 31;
    const int wid  = tid >> 5;

    // ---------------- Phase A: masked reduction over time ----------------
    float accx[S], accm[S];
#pragma unroll
    for (int s = 0; s < S; s++) { accx[s] = 0.f; accm[s] = 0.f; }
    float acct = 0.f, accd = 0.f;

    const float4* __restrict__ x4 = (const float4*)x + (size_t)b * S * G;
    const int4*   __restrict__ m4 = (const int4*)smask + (size_t)b * S * G;
    const float4* __restrict__ t4 = (const float4*)time_in + (size_t)b * G;

#pragma unroll 1
    for (int g = tid; g < G; g += NT) {
        float4 tv = t4[g];
        bool v0 = false, v1 = false, v2 = false, v3 = false;
#pragma unroll
        for (int s = 0; s < S; s++) {
            const int idx = s * G + g;
            float4 xv = x4[idx];
            int4   mv = m4[idx];
            // Feature sums need no mask: if the timestep is invalid, every
            // feature at that step is exactly 0 by construction.
            accx[s] += (xv.x + xv.y) + (xv.z + xv.w);
            accm[s] += (float)((mv.x + mv.y) + (mv.z + mv.w));
            v0 |= (xv.x != 0.f) | (mv.x != 0);
            v1 |= (xv.y != 0.f) | (mv.y != 0);
            v2 |= (xv.z != 0.f) | (mv.z != 0);
            v3 |= (xv.w != 0.f) | (mv.w != 0);
        }
        const float f0 = v0 ? 1.f : 0.f, f1 = v1 ? 1.f : 0.f;
        const float f2 = v2 ? 1.f : 0.f, f3 = v3 ? 1.f : 0.f;
        accd += (f0 + f1) + (f2 + f3);
        acct += (f0 * tv.x + f1 * tv.y) + (f2 * tv.z + f3 * tv.w);
    }

    // warp-level butterfly reduce every accumulator, lane0 -> smem
#pragma unroll
    for (int s = 0; s < S; s++) {
        float vx = warp_sum(accx[s]);
        float vm = warp_sum(accm[s]);
        if (lane == 0) { red[wid][s] = vx; red[wid][S + s] = vm; }
    }
    {
        float vt = warp_sum(acct);
        float vd = warp_sum(accd);
        if (lane == 0) { red[wid][F2] = vt; red[wid][F2 + 1] = vd; }
    }
    __syncthreads();

    if (tid < F2 + 2) {
        float v = 0.f;
#pragma unroll
        for (int w = 0; w < NW; w++) v += red[w][tid];
        if (tid < F2)            sfeat[tid] = v;
        else                     ssum[tid - F2] = v;   // [0]=time sum, [1]=denom
    }
    __syncthreads();

    if (tid == 0) {
        float dn  = ssum[1];
        float inv = 1.f / fmaxf(dn, 1e-9f);
        s_inv = inv;
        s_r   = dn * inv;        // 1.0 normally, 0.0 if no valid step
        s_ts  = ssum[0] * inv;   // mean masked time
    }
    __syncthreads();

    const float inv = s_inv, r = s_r, ts = s_ts;

    // ---------------- Phase B: pooled embedding + static embedding ----------------
    {
        // thread tid == output channel d (0..255); W_sensor read coalesced
        float acc = 0.f;
#pragma unroll
        for (int f = 0; f < F2; f++)
            acc = fmaf(sfeat[f], W_sensor[f * D + tid], acc);
        float p = acc * inv
                + r * (b_sensor[tid] + b_time[tid])
                + ts * W_time[tid];
        scomb[tid] = p;
    }
    if (tid < STC) {
        float acc = b_static[tid];
#pragma unroll
        for (int k = 0; k < STC; k++)
            acc = fmaf(static_in[b * STC + k], W_static[k * STC + tid], acc);
        scomb[D + tid] = acc;
    }
    __syncthreads();

    // ---------------- Phase C: merge (ReLU) + classifier ----------------
    float p0 = 0.f, p1 = 0.f;
    for (int j = tid; j < MERGED; j += NT) {
        float acc = b_merge[j];
#pragma unroll 8
        for (int k = 0; k < MERGED; k++)
            acc = fmaf(scomb[k], W_merge[k * MERGED + j], acc);
        acc = fmaxf(acc, 0.f);
        p0 = fmaf(acc, W_cls[j * C + 0], p0);
        p1 = fmaf(acc, W_cls[j * C + 1], p1);
    }
    p0 = warp_sum(p0);
    p1 = warp_sum(p1);
    if (lane == 0) { ored[wid][0] = p0; ored[wid][1] = p1; }
    __syncthreads();

    if (tid == 0) {
        float o0 = b_cls[0], o1 = b_cls[1];
#pragma unroll
        for (int w = 0; w < NW; w++) { o0 += ored[w][0]; o1 += ored[w][1]; }
        out[b * C + 0] = o0;
        out[b * C + 1] = o1;
    }
}

extern "C" void kernel_launch(void* const* d_in, const int* in_sizes, int n_in,
                              void* d_out, int out_size)
{
    const float* x        = (const float*)d_in[0];
    const float* stat     = (const float*)d_in[1];
    const float* time_in  = (const float*)d_in[2];
    const int*   smask    = (const int*)  d_in[3];
    const float* W_sensor = (const float*)d_in[4];
    const float* b_sensor = (const float*)d_in[5];
    const float* W_time   = (const float*)d_in[6];
    const float* b_time   = (const float*)d_in[7];
    const float* W_static = (const float*)d_in[8];
    const float* b_static = (const float*)d_in[9];
    const float* W_merge  = (const float*)d_in[10];
    const float* b_merge  = (const float*)d_in[11];
    const float* W_cls    = (const float*)d_in[12];
    const float* b_cls    = (const float*)d_in[13];
    float* out = (float*)d_out;

    enc_cls_fused_kernel<<<B, NT>>>(x, stat, time_in, smask,
                                    W_sensor, b_sensor, W_time, b_time,
                                    W_static, b_static, W_merge, b_merge,
                                    W_cls, b_cls, out);
}